// round 1
// baseline (speedup 1.0000x reference)
#include <cuda_runtime.h>
#include <math.h>

#define BB 4
#define TT 4096
#define DD 384
#define HD 64
#define BQ 64
#define BS 32

// Scratch (allocation-free): q,k: 4MB each; v: 25MB
__device__ float g_q[(size_t)BB * TT * HD];
__device__ float g_k[(size_t)BB * TT * HD];
__device__ float g_v[(size_t)BB * TT * DD];

// Y[M,N] = X[M,Kd] @ W[N,Kd]^T   (both row-major, Kd contiguous)
// BM=BN=64, BK=16, 256 threads, 4x4 per thread.
// which: 0 -> g_q, 1 -> g_k, 2 -> g_v (avoids cudaGetSymbolAddress)
__global__ __launch_bounds__(256) void gemm_xwT(
    const float* __restrict__ X, const float* __restrict__ W,
    int M, int N, int Kd, int which)
{
    float* __restrict__ Y = (which == 0) ? g_q : (which == 1) ? g_k : g_v;

    __shared__ float Xs[16][64];
    __shared__ float Ws[16][64];

    const int bm = blockIdx.y;
    const int bn = blockIdx.x;
    const int tid = threadIdx.x;
    const int tr = tid >> 4;          // 0..15
    const int tc = tid & 15;          // 0..15
    const int lrow = tid >> 2;        // 0..63
    const int lcol = (tid & 3) << 2;  // 0,4,8,12

    float acc[4][4];
#pragma unroll
    for (int i = 0; i < 4; i++)
#pragma unroll
        for (int j = 0; j < 4; j++) acc[i][j] = 0.f;

    const float* Xp = X + (size_t)(bm * 64 + lrow) * Kd + lcol;
    const float* Wp = W + (size_t)(bn * 64 + lrow) * Kd + lcol;

    for (int k0 = 0; k0 < Kd; k0 += 16) {
        float4 xv = *(const float4*)(Xp + k0);
        float4 wv = *(const float4*)(Wp + k0);
        __syncthreads();
        Xs[lcol + 0][lrow] = xv.x; Xs[lcol + 1][lrow] = xv.y;
        Xs[lcol + 2][lrow] = xv.z; Xs[lcol + 3][lrow] = xv.w;
        Ws[lcol + 0][lrow] = wv.x; Ws[lcol + 1][lrow] = wv.y;
        Ws[lcol + 2][lrow] = wv.z; Ws[lcol + 3][lrow] = wv.w;
        __syncthreads();
#pragma unroll
        for (int kk = 0; kk < 16; kk++) {
            float4 xr = *(const float4*)&Xs[kk][tr << 2];
            float4 wr = *(const float4*)&Ws[kk][tc << 2];
            float xa[4] = {xr.x, xr.y, xr.z, xr.w};
            float wa[4] = {wr.x, wr.y, wr.z, wr.w};
#pragma unroll
            for (int i = 0; i < 4; i++)
#pragma unroll
                for (int j = 0; j < 4; j++) acc[i][j] += xa[i] * wa[j];
        }
    }
#pragma unroll
    for (int i = 0; i < 4; i++) {
        float4 o = make_float4(acc[i][0], acc[i][1], acc[i][2], acc[i][3]);
        *(float4*)&Y[(size_t)(bm * 64 + tr * 4 + i) * N + bn * 64 + tc * 4] = o;
    }
}

// Flash attention, fp32, causal. 64 queries/block, 256 threads.
// Thread (qi = tid>>3, lane = tid&7) owns queries (qi, qi+32) and
// output dims d = lane*4 + 32*i + c for i in [0,12), c in [0,4).
__global__ __launch_bounds__(256) void flash_fwd(float* __restrict__ O)
{
    __shared__ float qs[BQ][HD + 4];   // 68-float rows: 16B-aligned, conflict-free
    __shared__ float ks[BS][HD + 4];
    __shared__ float ps[BQ][BS + 1];

    const int b = blockIdx.y;
    const int qb = (int)gridDim.x - 1 - (int)blockIdx.x;  // heavy tiles first
    const int tid = threadIdx.x;
    const int qi = tid >> 3;     // 0..31
    const int lane = tid & 7;    // 0..7
    const int q0 = qb * BQ;

    const float* Qb = g_q + ((size_t)b * TT + q0) * HD;
    const float* Kb = g_k + (size_t)b * TT * HD;
    const float* Vb = g_v + (size_t)b * TT * DD;

    // Load q tile (64x64)
    for (int i = tid; i < BQ * HD / 4; i += 256) {
        int r = i >> 4;            // HD/4 = 16
        int c = (i & 15) << 2;
        float4 t4 = *(const float4*)&Qb[r * HD + c];
        qs[r][c] = t4.x; qs[r][c + 1] = t4.y; qs[r][c + 2] = t4.z; qs[r][c + 3] = t4.w;
    }

    float m_a = -1e30f, m_b = -1e30f, l_a = 0.f, l_b = 0.f;
    float4 acc_a[12], acc_b[12];
#pragma unroll
    for (int i = 0; i < 12; i++) {
        acc_a[i] = make_float4(0.f, 0.f, 0.f, 0.f);
        acc_b[i] = make_float4(0.f, 0.f, 0.f, 0.f);
    }

    const int nTiles = (q0 + BQ) / BS;
    for (int t = 0; t < nTiles; t++) {
        const int s0 = t * BS;
        __syncthreads();
        // Load k tile (32x64)
        for (int i = tid; i < BS * HD / 4; i += 256) {
            int r = i >> 4;
            int c = (i & 15) << 2;
            float4 t4 = *(const float4*)&Kb[(size_t)(s0 + r) * HD + c];
            ks[r][c] = t4.x; ks[r][c + 1] = t4.y; ks[r][c + 2] = t4.z; ks[r][c + 3] = t4.w;
        }
        __syncthreads();

        // Scores: 2 queries x 4 keys per thread
        float sc_a[4], sc_b[4];
#pragma unroll
        for (int j = 0; j < 4; j++) {
            int s = lane + 8 * j;
            float da = 0.f, db = 0.f;
#pragma unroll
            for (int dd = 0; dd < HD; dd += 4) {
                float4 kv = *(const float4*)&ks[s][dd];
                float4 qa = *(const float4*)&qs[qi][dd];
                float4 qv = *(const float4*)&qs[qi + 32][dd];
                da += kv.x * qa.x + kv.y * qa.y + kv.z * qa.z + kv.w * qa.w;
                db += kv.x * qv.x + kv.y * qv.y + kv.z * qv.z + kv.w * qv.w;
            }
            int sg = s0 + s;
            sc_a[j] = (sg <= q0 + qi)      ? da * 0.125f : -1e30f;
            sc_b[j] = (sg <= q0 + qi + 32) ? db * 0.125f : -1e30f;
        }

        // Row max across the 8-lane group
        float ma = fmaxf(fmaxf(sc_a[0], sc_a[1]), fmaxf(sc_a[2], sc_a[3]));
        float mb = fmaxf(fmaxf(sc_b[0], sc_b[1]), fmaxf(sc_b[2], sc_b[3]));
#pragma unroll
        for (int o = 4; o; o >>= 1) {
            ma = fmaxf(ma, __shfl_xor_sync(0xffffffffu, ma, o, 8));
            mb = fmaxf(mb, __shfl_xor_sync(0xffffffffu, mb, o, 8));
        }
        float mna = fmaxf(m_a, ma), mnb = fmaxf(m_b, mb);
        float ca = __expf(m_a - mna), cb = __expf(m_b - mnb);
        m_a = mna; m_b = mnb;

        float pa[4], pb[4];
        float suma = 0.f, sumb = 0.f;
#pragma unroll
        for (int j = 0; j < 4; j++) {
            pa[j] = __expf(sc_a[j] - mna); suma += pa[j];
            pb[j] = __expf(sc_b[j] - mnb); sumb += pb[j];
        }
#pragma unroll
        for (int o = 4; o; o >>= 1) {
            suma += __shfl_xor_sync(0xffffffffu, suma, o, 8);
            sumb += __shfl_xor_sync(0xffffffffu, sumb, o, 8);
        }
        l_a = l_a * ca + suma;
        l_b = l_b * cb + sumb;

#pragma unroll
        for (int i = 0; i < 12; i++) {
            acc_a[i].x *= ca; acc_a[i].y *= ca; acc_a[i].z *= ca; acc_a[i].w *= ca;
            acc_b[i].x *= cb; acc_b[i].y *= cb; acc_b[i].z *= cb; acc_b[i].w *= cb;
        }
#pragma unroll
        for (int j = 0; j < 4; j++) {
            ps[qi][lane + 8 * j] = pa[j];
            ps[qi + 32][lane + 8 * j] = pb[j];
        }
        __syncwarp();

        // PV: V read directly from global (L1/L2-resident), float4
        const float* Vt = Vb + (size_t)s0 * DD;
        for (int s = 0; s < BS; s++) {
            float pas = ps[qi][s];
            float pbs = ps[qi + 32][s];
            const float4* vr = (const float4*)(Vt + (size_t)s * DD);
#pragma unroll
            for (int i = 0; i < 12; i++) {
                float4 v4 = vr[lane + 8 * i];
                acc_a[i].x += pas * v4.x; acc_a[i].y += pas * v4.y;
                acc_a[i].z += pas * v4.z; acc_a[i].w += pas * v4.w;
                acc_b[i].x += pbs * v4.x; acc_b[i].y += pbs * v4.y;
                acc_b[i].z += pbs * v4.z; acc_b[i].w += pbs * v4.w;
            }
        }
        __syncwarp();
    }

    const float ia = 1.f / l_a;
    const float ib = 1.f / l_b;
    float* Oa = O + ((size_t)b * TT + q0 + qi) * DD;
    float* Ob = O + ((size_t)b * TT + q0 + qi + 32) * DD;
#pragma unroll
    for (int i = 0; i < 12; i++) {
        float4 oa = make_float4(acc_a[i].x * ia, acc_a[i].y * ia, acc_a[i].z * ia, acc_a[i].w * ia);
        float4 ob = make_float4(acc_b[i].x * ib, acc_b[i].y * ib, acc_b[i].z * ib, acc_b[i].w * ib);
        *(float4*)&Oa[lane * 4 + 32 * i] = oa;
        *(float4*)&Ob[lane * 4 + 32 * i] = ob;
    }
}

extern "C" void kernel_launch(void* const* d_in, const int* in_sizes, int n_in,
                              void* d_out, int out_size)
{
    const float* x  = (const float*)d_in[0];
    const float* Wk = (const float*)d_in[1];
    const float* Wq = (const float*)d_in[2];
    const float* Wv = (const float*)d_in[3];
    float* out = (float*)d_out;

    dim3 th(256);
    // M = B*T = 16384 -> 256 row tiles of 64
    gemm_xwT<<<dim3(1, 256), th>>>(x, Wq, BB * TT, HD, DD, 0);
    gemm_xwT<<<dim3(1, 256), th>>>(x, Wk, BB * TT, HD, DD, 1);
    gemm_xwT<<<dim3(6, 256), th>>>(x, Wv, BB * TT, DD, DD, 2);
    flash_fwd<<<dim3(TT / BQ, BB), th>>>(out);
}

// round 2
// speedup vs baseline: 4.6702x; 4.6702x over previous
#include <cuda_runtime.h>
#include <math.h>
#include <stdint.h>

#define BB 4
#define TT 4096
#define DD 384
#define HD 64
#define BQ 64
#define BS 32

// Scratch (allocation-free)
__device__ float g_q[(size_t)BB * TT * HD];
__device__ float g_k[(size_t)BB * TT * HD];
__device__ float g_v[(size_t)BB * TT * DD];

// ---------------- projection GEMM (fp32 SIMT, unchanged) ----------------
__global__ __launch_bounds__(256) void gemm_xwT(
    const float* __restrict__ X, const float* __restrict__ W,
    int M, int N, int Kd, int which)
{
    float* __restrict__ Y = (which == 0) ? g_q : (which == 1) ? g_k : g_v;

    __shared__ float Xs[16][64];
    __shared__ float Ws[16][64];

    const int bm = blockIdx.y;
    const int bn = blockIdx.x;
    const int tid = threadIdx.x;
    const int tr = tid >> 4;
    const int tc = tid & 15;
    const int lrow = tid >> 2;
    const int lcol = (tid & 3) << 2;

    float acc[4][4];
#pragma unroll
    for (int i = 0; i < 4; i++)
#pragma unroll
        for (int j = 0; j < 4; j++) acc[i][j] = 0.f;

    const float* Xp = X + (size_t)(bm * 64 + lrow) * Kd + lcol;
    const float* Wp = W + (size_t)(bn * 64 + lrow) * Kd + lcol;

    for (int k0 = 0; k0 < Kd; k0 += 16) {
        float4 xv = *(const float4*)(Xp + k0);
        float4 wv = *(const float4*)(Wp + k0);
        __syncthreads();
        Xs[lcol + 0][lrow] = xv.x; Xs[lcol + 1][lrow] = xv.y;
        Xs[lcol + 2][lrow] = xv.z; Xs[lcol + 3][lrow] = xv.w;
        Ws[lcol + 0][lrow] = wv.x; Ws[lcol + 1][lrow] = wv.y;
        Ws[lcol + 2][lrow] = wv.z; Ws[lcol + 3][lrow] = wv.w;
        __syncthreads();
#pragma unroll
        for (int kk = 0; kk < 16; kk++) {
            float4 xr = *(const float4*)&Xs[kk][tr << 2];
            float4 wr = *(const float4*)&Ws[kk][tc << 2];
            float xa[4] = {xr.x, xr.y, xr.z, xr.w};
            float wa[4] = {wr.x, wr.y, wr.z, wr.w};
#pragma unroll
            for (int i = 0; i < 4; i++)
#pragma unroll
                for (int j = 0; j < 4; j++) acc[i][j] += xa[i] * wa[j];
        }
    }
#pragma unroll
    for (int i = 0; i < 4; i++) {
        float4 o = make_float4(acc[i][0], acc[i][1], acc[i][2], acc[i][3]);
        *(float4*)&Y[(size_t)(bm * 64 + tr * 4 + i) * N + bn * 64 + tc * 4] = o;
    }
}

// ---------------- tf32 tensor-core flash attention ----------------
// smem layout (floats), padded strides chosen conflict-free (verified mod 32)
#define VS_STRIDE 392
#define KS_STRIDE 68
#define PS_STRIDE 36
#define VS_TILE (32 * VS_STRIDE)
#define KS_TILE (32 * KS_STRIDE)
#define VS_OFF 0
#define KS_OFF (2 * VS_TILE)
#define PS_OFF (KS_OFF + 2 * KS_TILE)
#define SMEM_FLOATS (PS_OFF + 8 * 16 * PS_STRIDE)
#define SMEM_BYTES (SMEM_FLOATS * 4)

__device__ __forceinline__ uint32_t tf32r(float f) {
    uint32_t u;
    asm("cvt.rna.tf32.f32 %0, %1;" : "=r"(u) : "f"(f));
    return u;
}

__device__ __forceinline__ void mma8(float* c, const uint32_t* a, uint32_t b0, uint32_t b1) {
    asm volatile(
        "mma.sync.aligned.m16n8k8.row.col.f32.tf32.tf32.f32 "
        "{%0,%1,%2,%3}, {%4,%5,%6,%7}, {%8,%9}, {%0,%1,%2,%3};\n"
        : "+f"(c[0]), "+f"(c[1]), "+f"(c[2]), "+f"(c[3])
        : "r"(a[0]), "r"(a[1]), "r"(a[2]), "r"(a[3]), "r"(b0), "r"(b1));
}

__device__ __forceinline__ void cp16(uint32_t dsh, const void* src) {
    asm volatile("cp.async.cg.shared.global [%0], [%1], 16;\n" :: "r"(dsh), "l"(src));
}

__device__ __forceinline__ void stage_tile(float* sm, const float* Kb, const float* Vb,
                                           int s0, int buf, int tid)
{
    uint32_t vbase = (uint32_t)__cvta_generic_to_shared(sm + VS_OFF + buf * VS_TILE);
    uint32_t kbase = (uint32_t)__cvta_generic_to_shared(sm + KS_OFF + buf * KS_TILE);
#pragma unroll
    for (int it = 0; it < 2; it++) {              // K: 32x64 = 512 float4
        int i = tid + 256 * it;
        int r = i >> 4, c = (i & 15) << 2;
        cp16(kbase + (uint32_t)(r * KS_STRIDE + c) * 4, Kb + (size_t)(s0 + r) * HD + c);
    }
#pragma unroll
    for (int it = 0; it < 12; it++) {             // V: 32x384 = 3072 float4
        int i = tid + 256 * it;
        int r = i / 96, c = (i % 96) << 2;
        cp16(vbase + (uint32_t)(r * VS_STRIDE + c) * 4, Vb + (size_t)(s0 + r) * DD + c);
    }
}

__global__ void __launch_bounds__(256, 1) flash2(float* __restrict__ O)
{
    extern __shared__ float sm[];
    const int b = blockIdx.y;
    const int qb = (int)gridDim.x - 1 - (int)blockIdx.x;   // heavy tiles first
    const int q0 = qb * BQ;
    const int tid = threadIdx.x;
    const int w = tid >> 5, l = tid & 31;
    const int qw = w >> 1, dw = w & 1;
    const int g = l >> 2, q4 = l & 3;

    const float* Qb = g_q + ((size_t)b * TT + q0) * HD;
    const float* Kb = g_k + (size_t)b * TT * HD;
    const float* Vb = g_v + (size_t)b * TT * DD;

    float* Ps = sm + PS_OFF + w * (16 * PS_STRIDE);

    // Q fragments (rounded to tf32), held in registers for the whole kernel
    uint32_t qa[8][4];
    const int qr0 = qw * 16 + g;
#pragma unroll
    for (int kk = 0; kk < 8; kk++) {
        qa[kk][0] = tf32r(Qb[(size_t)qr0 * HD + 8 * kk + q4]);
        qa[kk][1] = tf32r(Qb[(size_t)(qr0 + 8) * HD + 8 * kk + q4]);
        qa[kk][2] = tf32r(Qb[(size_t)qr0 * HD + 8 * kk + q4 + 4]);
        qa[kk][3] = tf32r(Qb[(size_t)(qr0 + 8) * HD + 8 * kk + q4 + 4]);
    }

    float co[24][4];
#pragma unroll
    for (int j = 0; j < 24; j++) { co[j][0] = co[j][1] = co[j][2] = co[j][3] = 0.f; }
    float m0 = -1e30f, m1 = -1e30f, l0 = 0.f, l1 = 0.f;

    const int nT = (q0 + BQ) / BS;
    const int q_last = q0 + qw * 16 + 15;
    const int row0 = q0 + qw * 16 + g;
    const int row1 = row0 + 8;
    const int d0base = dw * 192;

    stage_tile(sm, Kb, Vb, 0, 0, tid);
    asm volatile("cp.async.commit_group;\n");

    for (int t = 0; t < nT; t++) {
        __syncthreads();   // all warps done with buffer (t+1)&1 from tile t-1
        if (t + 1 < nT) {
            stage_tile(sm, Kb, Vb, (t + 1) * BS, (t + 1) & 1, tid);
            asm volatile("cp.async.commit_group;\n");
            asm volatile("cp.async.wait_group 1;\n");
        } else {
            asm volatile("cp.async.wait_group 0;\n");
        }
        __syncthreads();   // tile t data visible

        const int s0 = t * BS;
        if (s0 <= q_last) {
            const float* Ks = sm + KS_OFF + (t & 1) * KS_TILE;
            const float* Vs = sm + VS_OFF + (t & 1) * VS_TILE;

            // ---- S = Q K^T (16x32 per warp) ----
            float cs[4][4];
#pragma unroll
            for (int j = 0; j < 4; j++) { cs[j][0] = cs[j][1] = cs[j][2] = cs[j][3] = 0.f; }
#pragma unroll
            for (int kk = 0; kk < 8; kk++) {
#pragma unroll
                for (int j = 0; j < 4; j++) {
                    const float* kp = Ks + (8 * j + g) * KS_STRIDE + 8 * kk + q4;
                    mma8(cs[j], qa[kk], __float_as_uint(kp[0]), __float_as_uint(kp[4]));
                }
            }

            // ---- scale + causal mask + row max ----
            const bool needmask = (s0 + 31 > q0 + qw * 16);
            float mx0 = -1e30f, mx1 = -1e30f;
#pragma unroll
            for (int j = 0; j < 4; j++) {
                int c0 = s0 + 8 * j + 2 * q4;
                float s00 = cs[j][0] * 0.125f, s01 = cs[j][1] * 0.125f;
                float s10 = cs[j][2] * 0.125f, s11 = cs[j][3] * 0.125f;
                if (needmask) {
                    if (c0 > row0)     s00 = -1e30f;
                    if (c0 + 1 > row0) s01 = -1e30f;
                    if (c0 > row1)     s10 = -1e30f;
                    if (c0 + 1 > row1) s11 = -1e30f;
                }
                cs[j][0] = s00; cs[j][1] = s01; cs[j][2] = s10; cs[j][3] = s11;
                mx0 = fmaxf(mx0, fmaxf(s00, s01));
                mx1 = fmaxf(mx1, fmaxf(s10, s11));
            }
            mx0 = fmaxf(mx0, __shfl_xor_sync(0xffffffffu, mx0, 1, 4));
            mx0 = fmaxf(mx0, __shfl_xor_sync(0xffffffffu, mx0, 2, 4));
            mx1 = fmaxf(mx1, __shfl_xor_sync(0xffffffffu, mx1, 1, 4));
            mx1 = fmaxf(mx1, __shfl_xor_sync(0xffffffffu, mx1, 2, 4));

            float mn0 = fmaxf(m0, mx0), mn1 = fmaxf(m1, mx1);
            float cr0 = __expf(m0 - mn0), cr1 = __expf(m1 - mn1);
            m0 = mn0; m1 = mn1;

            // ---- P = exp(S - m), write tf32 P to per-warp smem ----
            float sum0 = 0.f, sum1 = 0.f;
#pragma unroll
            for (int j = 0; j < 4; j++) {
                float p00 = __expf(cs[j][0] - mn0), p01 = __expf(cs[j][1] - mn0);
                float p10 = __expf(cs[j][2] - mn1), p11 = __expf(cs[j][3] - mn1);
                sum0 += p00 + p01; sum1 += p10 + p11;
                *(float2*)&Ps[g * PS_STRIDE + 8 * j + 2 * q4] =
                    make_float2(__uint_as_float(tf32r(p00)), __uint_as_float(tf32r(p01)));
                *(float2*)&Ps[(g + 8) * PS_STRIDE + 8 * j + 2 * q4] =
                    make_float2(__uint_as_float(tf32r(p10)), __uint_as_float(tf32r(p11)));
            }
            sum0 += __shfl_xor_sync(0xffffffffu, sum0, 1, 4);
            sum0 += __shfl_xor_sync(0xffffffffu, sum0, 2, 4);
            sum1 += __shfl_xor_sync(0xffffffffu, sum1, 1, 4);
            sum1 += __shfl_xor_sync(0xffffffffu, sum1, 2, 4);
            l0 = l0 * cr0 + sum0;
            l1 = l1 * cr1 + sum1;

#pragma unroll
            for (int j = 0; j < 24; j++) {
                co[j][0] *= cr0; co[j][1] *= cr0;
                co[j][2] *= cr1; co[j][3] *= cr1;
            }
            __syncwarp();

            // ---- O += P V (16 x 192 per warp) ----
#pragma unroll
            for (int kk = 0; kk < 4; kk++) {
                uint32_t a[4];
                a[0] = __float_as_uint(Ps[g * PS_STRIDE + 8 * kk + q4]);
                a[1] = __float_as_uint(Ps[(g + 8) * PS_STRIDE + 8 * kk + q4]);
                a[2] = __float_as_uint(Ps[g * PS_STRIDE + 8 * kk + q4 + 4]);
                a[3] = __float_as_uint(Ps[(g + 8) * PS_STRIDE + 8 * kk + q4 + 4]);
                const float* Vk = Vs + (8 * kk + q4) * VS_STRIDE + d0base + g;
#pragma unroll
                for (int j = 0; j < 24; j++) {
                    mma8(co[j], a, __float_as_uint(Vk[8 * j]),
                                   __float_as_uint(Vk[4 * VS_STRIDE + 8 * j]));
                }
            }
        }
    }

    // ---- epilogue ----
    const float i0 = 1.f / l0, i1 = 1.f / l1;
    float* O0 = O + ((size_t)b * TT + row0) * DD + d0base;
    float* O1 = O + ((size_t)b * TT + row1) * DD + d0base;
#pragma unroll
    for (int j = 0; j < 24; j++) {
        *(float2*)&O0[8 * j + 2 * q4] = make_float2(co[j][0] * i0, co[j][1] * i0);
        *(float2*)&O1[8 * j + 2 * q4] = make_float2(co[j][2] * i1, co[j][3] * i1);
    }
}

extern "C" void kernel_launch(void* const* d_in, const int* in_sizes, int n_in,
                              void* d_out, int out_size)
{
    const float* x  = (const float*)d_in[0];
    const float* Wk = (const float*)d_in[1];
    const float* Wq = (const float*)d_in[2];
    const float* Wv = (const float*)d_in[3];
    float* out = (float*)d_out;

    dim3 th(256);
    gemm_xwT<<<dim3(1, 256), th>>>(x, Wq, BB * TT, HD, DD, 0);
    gemm_xwT<<<dim3(1, 256), th>>>(x, Wk, BB * TT, HD, DD, 1);
    gemm_xwT<<<dim3(6, 256), th>>>(x, Wv, BB * TT, DD, DD, 2);

    cudaFuncSetAttribute(flash2, cudaFuncAttributeMaxDynamicSharedMemorySize, SMEM_BYTES);
    flash2<<<dim3(TT / BQ, BB), th, SMEM_BYTES>>>(out);
}

// round 3
// speedup vs baseline: 6.1112x; 1.3085x over previous
#include <cuda_runtime.h>
#include <math.h>
#include <stdint.h>

#define BB 4
#define TT 4096
#define DD 384
#define HD 64
#define BQ 64
#define BS 32

// Scratch (allocation-free)
__device__ float g_q[(size_t)BB * TT * HD];
__device__ float g_k[(size_t)BB * TT * HD];
__device__ float g_v[(size_t)BB * TT * DD];

__device__ __forceinline__ uint32_t tf32r(float f) {
    uint32_t u;
    asm("cvt.rna.tf32.f32 %0, %1;" : "=r"(u) : "f"(f));
    return u;
}

__device__ __forceinline__ void mma8(float* c, const uint32_t* a, uint32_t b0, uint32_t b1) {
    asm volatile(
        "mma.sync.aligned.m16n8k8.row.col.f32.tf32.tf32.f32 "
        "{%0,%1,%2,%3}, {%4,%5,%6,%7}, {%8,%9}, {%0,%1,%2,%3};\n"
        : "+f"(c[0]), "+f"(c[1]), "+f"(c[2]), "+f"(c[3])
        : "r"(a[0]), "r"(a[1]), "r"(a[2]), "r"(a[3]), "r"(b0), "r"(b1));
}

__device__ __forceinline__ void cp16(uint32_t dsh, const void* src) {
    asm volatile("cp.async.cg.shared.global [%0], [%1], 16;\n" :: "r"(dsh), "l"(src));
}

// ---------------- tf32 mma projection GEMM ----------------
// Y[M,N] = X[M,384] @ W[N,384]^T, 128x64 CTA tile, BK=32, double buffered.
// Outputs are rna-rounded to tf32 so the attention kernel's truncation is lossless.
#define PK 384
#define PXS 36          // padded row stride for X tile (128 x 36)
#define PWS 36          // padded row stride for W tile (64 x 36)
#define PX_TILE (128 * PXS)
#define PW_TILE (64 * PWS)
#define PROJ_SMEM_FLOATS (2 * (PX_TILE + PW_TILE))
#define PROJ_SMEM_BYTES (PROJ_SMEM_FLOATS * 4)

__device__ __forceinline__ void proj_stage(float* sm, const float* X, const float* W,
                                           int bm, int bn, int k0, int buf, int tid)
{
    float* xb = sm + buf * (PX_TILE + PW_TILE);
    float* wb = xb + PX_TILE;
    uint32_t xbase = (uint32_t)__cvta_generic_to_shared(xb);
    uint32_t wbase = (uint32_t)__cvta_generic_to_shared(wb);
#pragma unroll
    for (int it = 0; it < 4; it++) {            // X: 128 rows x 32 = 1024 float4
        int i = tid + 256 * it;
        int r = i >> 3, c = (i & 7) << 2;
        cp16(xbase + (uint32_t)(r * PXS + c) * 4,
             X + (size_t)(bm * 128 + r) * PK + k0 + c);
    }
#pragma unroll
    for (int it = 0; it < 2; it++) {            // W: 64 rows x 32 = 512 float4
        int i = tid + 256 * it;
        int r = i >> 3, c = (i & 7) << 2;
        cp16(wbase + (uint32_t)(r * PWS + c) * 4,
             W + (size_t)(bn * 64 + r) * PK + k0 + c);
    }
}

__global__ void __launch_bounds__(256) proj_gemm(
    const float* __restrict__ X, const float* __restrict__ W0,
    const float* __restrict__ W1, int N, int which_base)
{
    extern __shared__ float sm[];
    const int z = blockIdx.z;
    const float* W = z ? W1 : W0;
    const int which = which_base + z;
    float* __restrict__ Y = (which == 0) ? g_q : (which == 1) ? g_k : g_v;

    const int bm = blockIdx.y;
    const int bn = blockIdx.x;
    const int tid = threadIdx.x;
    const int w = tid >> 5, l = tid & 31;
    const int wm = w >> 1, wn = w & 1;
    const int g = l >> 2, q4 = l & 3;

    float c[2][4][4];
#pragma unroll
    for (int mt = 0; mt < 2; mt++)
#pragma unroll
        for (int j = 0; j < 4; j++) { c[mt][j][0] = c[mt][j][1] = c[mt][j][2] = c[mt][j][3] = 0.f; }

    proj_stage(sm, X, W, bm, bn, 0, 0, tid);
    asm volatile("cp.async.commit_group;\n");

    const int nC = PK / 32;   // 12
    for (int cc = 0; cc < nC; cc++) {
        __syncthreads();
        if (cc + 1 < nC) {
            proj_stage(sm, X, W, bm, bn, (cc + 1) * 32, (cc + 1) & 1, tid);
            asm volatile("cp.async.commit_group;\n");
            asm volatile("cp.async.wait_group 1;\n");
        } else {
            asm volatile("cp.async.wait_group 0;\n");
        }
        __syncthreads();

        const float* xb = sm + (cc & 1) * (PX_TILE + PW_TILE);
        const float* wb = xb + PX_TILE;
#pragma unroll
        for (int kk = 0; kk < 4; kk++) {
            const int k = kk * 8;
            uint32_t a[2][4];
#pragma unroll
            for (int mt = 0; mt < 2; mt++) {
                int r0 = wm * 32 + 16 * mt + g;
                a[mt][0] = tf32r(xb[r0 * PXS + k + q4]);
                a[mt][1] = tf32r(xb[(r0 + 8) * PXS + k + q4]);
                a[mt][2] = tf32r(xb[r0 * PXS + k + q4 + 4]);
                a[mt][3] = tf32r(xb[(r0 + 8) * PXS + k + q4 + 4]);
            }
            uint32_t bfr[4][2];
#pragma unroll
            for (int j = 0; j < 4; j++) {
                int n = wn * 32 + 8 * j + g;
                bfr[j][0] = tf32r(wb[n * PWS + k + q4]);
                bfr[j][1] = tf32r(wb[n * PWS + k + q4 + 4]);
            }
#pragma unroll
            for (int mt = 0; mt < 2; mt++)
#pragma unroll
                for (int j = 0; j < 4; j++)
                    mma8(c[mt][j], a[mt], bfr[j][0], bfr[j][1]);
        }
    }

    // Epilogue: rna-round to tf32 so downstream tf32 use is exact
#pragma unroll
    for (int mt = 0; mt < 2; mt++) {
        int r0 = bm * 128 + wm * 32 + 16 * mt + g;
#pragma unroll
        for (int j = 0; j < 4; j++) {
            int col = bn * 64 + wn * 32 + 8 * j + 2 * q4;
            *(float2*)&Y[(size_t)r0 * N + col] =
                make_float2(__uint_as_float(tf32r(c[mt][j][0])), __uint_as_float(tf32r(c[mt][j][1])));
            *(float2*)&Y[(size_t)(r0 + 8) * N + col] =
                make_float2(__uint_as_float(tf32r(c[mt][j][2])), __uint_as_float(tf32r(c[mt][j][3])));
        }
    }
}

// ---------------- tf32 tensor-core flash attention (unchanged) ----------------
#define VS_STRIDE 392
#define KS_STRIDE 68
#define PS_STRIDE 36
#define VS_TILE (32 * VS_STRIDE)
#define KS_TILE (32 * KS_STRIDE)
#define VS_OFF 0
#define KS_OFF (2 * VS_TILE)
#define PS_OFF (KS_OFF + 2 * KS_TILE)
#define SMEM_FLOATS (PS_OFF + 8 * 16 * PS_STRIDE)
#define SMEM_BYTES (SMEM_FLOATS * 4)

__device__ __forceinline__ void stage_tile(float* sm, const float* Kb, const float* Vb,
                                           int s0, int buf, int tid)
{
    uint32_t vbase = (uint32_t)__cvta_generic_to_shared(sm + VS_OFF + buf * VS_TILE);
    uint32_t kbase = (uint32_t)__cvta_generic_to_shared(sm + KS_OFF + buf * KS_TILE);
#pragma unroll
    for (int it = 0; it < 2; it++) {
        int i = tid + 256 * it;
        int r = i >> 4, c = (i & 15) << 2;
        cp16(kbase + (uint32_t)(r * KS_STRIDE + c) * 4, Kb + (size_t)(s0 + r) * HD + c);
    }
#pragma unroll
    for (int it = 0; it < 12; it++) {
        int i = tid + 256 * it;
        int r = i / 96, c = (i % 96) << 2;
        cp16(vbase + (uint32_t)(r * VS_STRIDE + c) * 4, Vb + (size_t)(s0 + r) * DD + c);
    }
}

__global__ void __launch_bounds__(256, 1) flash2(float* __restrict__ O)
{
    extern __shared__ float sm[];
    const int b = blockIdx.y;
    const int qb = (int)gridDim.x - 1 - (int)blockIdx.x;
    const int q0 = qb * BQ;
    const int tid = threadIdx.x;
    const int w = tid >> 5, l = tid & 31;
    const int qw = w >> 1, dw = w & 1;
    const int g = l >> 2, q4 = l & 3;

    const float* Qb = g_q + ((size_t)b * TT + q0) * HD;
    const float* Kb = g_k + (size_t)b * TT * HD;
    const float* Vb = g_v + (size_t)b * TT * DD;

    float* Ps = sm + PS_OFF + w * (16 * PS_STRIDE);

    uint32_t qa[8][4];
    const int qr0 = qw * 16 + g;
#pragma unroll
    for (int kk = 0; kk < 8; kk++) {
        qa[kk][0] = tf32r(Qb[(size_t)qr0 * HD + 8 * kk + q4]);
        qa[kk][1] = tf32r(Qb[(size_t)(qr0 + 8) * HD + 8 * kk + q4]);
        qa[kk][2] = tf32r(Qb[(size_t)qr0 * HD + 8 * kk + q4 + 4]);
        qa[kk][3] = tf32r(Qb[(size_t)(qr0 + 8) * HD + 8 * kk + q4 + 4]);
    }

    float co[24][4];
#pragma unroll
    for (int j = 0; j < 24; j++) { co[j][0] = co[j][1] = co[j][2] = co[j][3] = 0.f; }
    float m0 = -1e30f, m1 = -1e30f, l0 = 0.f, l1 = 0.f;

    const int nT = (q0 + BQ) / BS;
    const int q_last = q0 + qw * 16 + 15;
    const int row0 = q0 + qw * 16 + g;
    const int row1 = row0 + 8;
    const int d0base = dw * 192;

    stage_tile(sm, Kb, Vb, 0, 0, tid);
    asm volatile("cp.async.commit_group;\n");

    for (int t = 0; t < nT; t++) {
        __syncthreads();
        if (t + 1 < nT) {
            stage_tile(sm, Kb, Vb, (t + 1) * BS, (t + 1) & 1, tid);
            asm volatile("cp.async.commit_group;\n");
            asm volatile("cp.async.wait_group 1;\n");
        } else {
            asm volatile("cp.async.wait_group 0;\n");
        }
        __syncthreads();

        const int s0 = t * BS;
        if (s0 <= q_last) {
            const float* Ks = sm + KS_OFF + (t & 1) * KS_TILE;
            const float* Vs = sm + VS_OFF + (t & 1) * VS_TILE;

            float cs[4][4];
#pragma unroll
            for (int j = 0; j < 4; j++) { cs[j][0] = cs[j][1] = cs[j][2] = cs[j][3] = 0.f; }
#pragma unroll
            for (int kk = 0; kk < 8; kk++) {
#pragma unroll
                for (int j = 0; j < 4; j++) {
                    const float* kp = Ks + (8 * j + g) * KS_STRIDE + 8 * kk + q4;
                    mma8(cs[j], qa[kk], __float_as_uint(kp[0]), __float_as_uint(kp[4]));
                }
            }

            const bool needmask = (s0 + 31 > q0 + qw * 16);
            float mx0 = -1e30f, mx1 = -1e30f;
#pragma unroll
            for (int j = 0; j < 4; j++) {
                int c0 = s0 + 8 * j + 2 * q4;
                float s00 = cs[j][0] * 0.125f, s01 = cs[j][1] * 0.125f;
                float s10 = cs[j][2] * 0.125f, s11 = cs[j][3] * 0.125f;
                if (needmask) {
                    if (c0 > row0)     s00 = -1e30f;
                    if (c0 + 1 > row0) s01 = -1e30f;
                    if (c0 > row1)     s10 = -1e30f;
                    if (c0 + 1 > row1) s11 = -1e30f;
                }
                cs[j][0] = s00; cs[j][1] = s01; cs[j][2] = s10; cs[j][3] = s11;
                mx0 = fmaxf(mx0, fmaxf(s00, s01));
                mx1 = fmaxf(mx1, fmaxf(s10, s11));
            }
            mx0 = fmaxf(mx0, __shfl_xor_sync(0xffffffffu, mx0, 1, 4));
            mx0 = fmaxf(mx0, __shfl_xor_sync(0xffffffffu, mx0, 2, 4));
            mx1 = fmaxf(mx1, __shfl_xor_sync(0xffffffffu, mx1, 1, 4));
            mx1 = fmaxf(mx1, __shfl_xor_sync(0xffffffffu, mx1, 2, 4));

            float mn0 = fmaxf(m0, mx0), mn1 = fmaxf(m1, mx1);
            float cr0 = __expf(m0 - mn0), cr1 = __expf(m1 - mn1);
            m0 = mn0; m1 = mn1;

            float sum0 = 0.f, sum1 = 0.f;
#pragma unroll
            for (int j = 0; j < 4; j++) {
                float p00 = __expf(cs[j][0] - mn0), p01 = __expf(cs[j][1] - mn0);
                float p10 = __expf(cs[j][2] - mn1), p11 = __expf(cs[j][3] - mn1);
                sum0 += p00 + p01; sum1 += p10 + p11;
                *(float2*)&Ps[g * PS_STRIDE + 8 * j + 2 * q4] =
                    make_float2(__uint_as_float(tf32r(p00)), __uint_as_float(tf32r(p01)));
                *(float2*)&Ps[(g + 8) * PS_STRIDE + 8 * j + 2 * q4] =
                    make_float2(__uint_as_float(tf32r(p10)), __uint_as_float(tf32r(p11)));
            }
            sum0 += __shfl_xor_sync(0xffffffffu, sum0, 1, 4);
            sum0 += __shfl_xor_sync(0xffffffffu, sum0, 2, 4);
            sum1 += __shfl_xor_sync(0xffffffffu, sum1, 1, 4);
            sum1 += __shfl_xor_sync(0xffffffffu, sum1, 2, 4);
            l0 = l0 * cr0 + sum0;
            l1 = l1 * cr1 + sum1;

#pragma unroll
            for (int j = 0; j < 24; j++) {
                co[j][0] *= cr0; co[j][1] *= cr0;
                co[j][2] *= cr1; co[j][3] *= cr1;
            }
            __syncwarp();

#pragma unroll
            for (int kk = 0; kk < 4; kk++) {
                uint32_t a[4];
                a[0] = __float_as_uint(Ps[g * PS_STRIDE + 8 * kk + q4]);
                a[1] = __float_as_uint(Ps[(g + 8) * PS_STRIDE + 8 * kk + q4]);
                a[2] = __float_as_uint(Ps[g * PS_STRIDE + 8 * kk + q4 + 4]);
                a[3] = __float_as_uint(Ps[(g + 8) * PS_STRIDE + 8 * kk + q4 + 4]);
                const float* Vk = Vs + (8 * kk + q4) * VS_STRIDE + d0base + g;
#pragma unroll
                for (int j = 0; j < 24; j++) {
                    mma8(co[j], a, __float_as_uint(Vk[8 * j]),
                                   __float_as_uint(Vk[4 * VS_STRIDE + 8 * j]));
                }
            }
        }
    }

    const float i0 = 1.f / l0, i1 = 1.f / l1;
    float* O0 = O + ((size_t)b * TT + row0) * DD + d0base;
    float* O1 = O + ((size_t)b * TT + row1) * DD + d0base;
#pragma unroll
    for (int j = 0; j < 24; j++) {
        *(float2*)&O0[8 * j + 2 * q4] = make_float2(co[j][0] * i0, co[j][1] * i0);
        *(float2*)&O1[8 * j + 2 * q4] = make_float2(co[j][2] * i1, co[j][3] * i1);
    }
}

extern "C" void kernel_launch(void* const* d_in, const int* in_sizes, int n_in,
                              void* d_out, int out_size)
{
    const float* x  = (const float*)d_in[0];
    const float* Wk = (const float*)d_in[1];
    const float* Wq = (const float*)d_in[2];
    const float* Wv = (const float*)d_in[3];
    float* out = (float*)d_out;

    dim3 th(256);
    cudaFuncSetAttribute(proj_gemm, cudaFuncAttributeMaxDynamicSharedMemorySize, PROJ_SMEM_BYTES);
    // q and k fused via gridDim.z; v separately (N=384)
    proj_gemm<<<dim3(1, 128, 2), th, PROJ_SMEM_BYTES>>>(x, Wq, Wk, HD, 0);
    proj_gemm<<<dim3(6, 128, 1), th, PROJ_SMEM_BYTES>>>(x, Wv, Wv, DD, 2);

    cudaFuncSetAttribute(flash2, cudaFuncAttributeMaxDynamicSharedMemorySize, SMEM_BYTES);
    flash2<<<dim3(TT / BQ, BB), th, SMEM_BYTES>>>(out);
}